// round 13
// baseline (speedup 1.0000x reference)
#include <cuda_runtime.h>
#include <stdint.h>

#define NROI    65536
#define NCASC   3
#define NBATCH  64
#define NROWS   (NBATCH * NCASC)
#define SLICES  16
#define SLICE_ELEMS (NROI / SLICES)        // 4096
#define TPB     128
#define NWARPS  (TPB / 32)                 // 4
#define WCHUNK  (SLICE_ELEMS / NWARPS)     // 1024 elements per warp
#define PCAP    64                         // pos candidates per (row,slice)
#define NCAP    64                         // neg candidates per (row,slice)
#define NSLOT   (SLICES * PCAP)            // 1024 candidate slots per row
#define VPT     (NSLOT / TPB)              // 8 candidate slots per thread
#define TPOSC   0.99f
#define TNEGC   0.99f
#define BITS_CAND 0x3F7AE148u              // bits(0.98) — safe lower bound
#define BITS_ONE  0x3F800000u              // bits(1.0)  — values strictly below

struct Keys { uint32_t k0[3]; uint32_t k1[3]; };

// per-(row,slice) partials — written unconditionally every run (no init pass)
__device__ float  g_pmax [NROWS * SLICES];   // max iou per slice
__device__ float  g_pomax[NROWS * SLICES];   // max overlap per slice
__device__ int    g_pelig[NROWS * SLICES];
__device__ int    g_pcnt [NROWS * SLICES];
__device__ int    g_ncnt [NROWS * SLICES];
__device__ float  g_posv [NROWS * NSLOT];
__device__ int    g_posi [NROWS * NSLOT];
__device__ float  g_negu [NROWS * NSLOT];
__device__ int    g_negj [NROWS * NSLOT];
__device__ int    g_arrive[NROWS];           // zero-init; reset by finalizer

__device__ const float c_POS_T[3] = {0.6f, 0.7f, 0.8f};
__device__ const float c_IOU_T[3] = {0.2f, 0.3f, 0.4f};
__device__ const float c_NEG_T[3] = {0.3f, 0.3f, 0.3f};

// ---------------------------------------------------------------------------
// JAX threefry2x32 (exact; verified rel_err = 0.0)
// ---------------------------------------------------------------------------
__host__ __device__ __forceinline__ void threefry2x32(
    uint32_t k0, uint32_t k1, uint32_t x0, uint32_t x1,
    uint32_t& o0, uint32_t& o1)
{
    uint32_t ks2 = k0 ^ k1 ^ 0x1BD11BDAu;
    x0 += k0; x1 += k1;
#define TFR(r) { x0 += x1; x1 = (x1 << (r)) | (x1 >> (32 - (r))); x1 ^= x0; }
    TFR(13) TFR(15) TFR(26) TFR(6)  x0 += k1;  x1 += ks2 + 1u;
    TFR(17) TFR(29) TFR(16) TFR(24) x0 += ks2; x1 += k0  + 2u;
    TFR(13) TFR(15) TFR(26) TFR(6)  x0 += k0;  x1 += k1  + 3u;
    TFR(17) TFR(29) TFR(16) TFR(24) x0 += k1;  x1 += ks2 + 4u;
    TFR(13) TFR(15) TFR(26) TFR(6)  x0 += ks2; x1 += k0  + 5u;
#undef TFR
    o0 = x0; o1 = x1;
}

__device__ __forceinline__ float u01(uint32_t k0, uint32_t k1, uint32_t idx)
{
    uint32_t a, c;
    threefry2x32(k0, k1, 0u, idx, a, c);
    uint32_t bits = a ^ c;
    return __uint_as_float((bits >> 9) | 0x3F800000u) - 1.0f;
}

// ---------------------------------------------------------------------------
// 128-thread block reduction helpers (4 warps; tiny barriers)
// ---------------------------------------------------------------------------
__device__ __forceinline__ int block_sum128(int c, int* s_ws)
{
    c = (int)__reduce_add_sync(0xFFFFFFFFu, (unsigned)c);
    if ((threadIdx.x & 31) == 0) s_ws[threadIdx.x >> 5] = c;
    __syncthreads();
    int tot = s_ws[0] + s_ws[1] + s_ws[2] + s_ws[3];
    __syncthreads();
    return tot;
}

__device__ __forceinline__ float block_max128(float v, float* s_wf)
{
    unsigned m = __reduce_max_sync(0xFFFFFFFFu, __float_as_uint(v)); // v >= 0
    if ((threadIdx.x & 31) == 0) s_wf[threadIdx.x >> 5] = __uint_as_float(m);
    __syncthreads();
    float r = fmaxf(fmaxf(s_wf[0], s_wf[1]), fmaxf(s_wf[2], s_wf[3]));
    __syncthreads();
    return r;
}

// kth-largest over VPT register slots/thread via binary search on float bits.
// Invalid slots masked to -1. Exact. Precondition: count(v>=lo_val) >= k.
__device__ float block_kth8(int k, const float (&v)[VPT],
                            unsigned lo, unsigned hi, int* s_ws)
{
    while (hi > lo) {
        unsigned mid = lo + ((hi - lo + 1u) >> 1);
        float t = __uint_as_float(mid);
        int c = 0;
#pragma unroll
        for (int s = 0; s < VPT; s++) c += (v[s] >= t);
        c = block_sum128(c, s_ws);
        if (c >= k) lo = mid; else hi = mid - 1u;
    }
    return __uint_as_float(lo);
}

// top_k[1] semantics: max if multiplicity >= 2, else largest strictly below.
__device__ float block_top2_8(const float (&v)[VPT], int* s_ws, float* s_wf)
{
    float m = 0.0f;
#pragma unroll
    for (int s = 0; s < VPT; s++) m = fmaxf(m, v[s]);
    m = block_max128(m, s_wf);
    int c = 0;
#pragma unroll
    for (int s = 0; s < VPT; s++) c += (v[s] >= m);
    c = block_sum128(c, s_ws);
    if (c >= 2) return m;
    float m2 = 0.0f;
#pragma unroll
    for (int s = 0; s < VPT; s++) m2 = fmaxf(m2, (v[s] < m) ? v[s] : 0.0f);
    return block_max128(m2, s_wf);
}

// ---------------------------------------------------------------------------
// Exact full-row fallbacks (statistically never run). 128-thread block.
// __noinline__ keeps their frames out of the hot path's register budget.
// ---------------------------------------------------------------------------
__device__ __noinline__ float kth_bs_iomask(int k, const float* ov,
                                            const float* io, float POS_T,
                                            int nopos, float mx, int* s_ws)
{
    unsigned lo = 0u, hi = 0x7F800000u;
    while (hi > lo) {
        unsigned mid = lo + ((hi - lo + 1u) >> 1);
        float t = __uint_as_float(mid);
        int c = 0;
        for (int j = threadIdx.x; j < NROI; j += TPB) {
            float o = ov[j], v = io[j];
            float im = nopos ? ((v >= mx) ? v : 0.0f)
                             : ((o >= POS_T) ? v : 0.0f);
            c += (im >= t);
        }
        c = block_sum128(c, s_ws);
        if (c >= k) lo = mid; else hi = mid - 1u;
    }
    return __uint_as_float(lo);
}

__device__ __noinline__ float kth_bs_score(int k, const float* ov, float NEG_T,
                                           uint32_t k0, uint32_t k1,
                                           uint32_t rng_base, int* s_ws)
{
    unsigned lo = 0u, hi = 0x7F800000u;
    while (hi > lo) {
        unsigned mid = lo + ((hi - lo + 1u) >> 1);
        float t = __uint_as_float(mid);
        int c = 0;
        for (int j = threadIdx.x; j < NROI; j += TPB) {
            float o = ov[j];
            if (o <= NEG_T) {
                float u = u01(k0, k1, rng_base + (uint32_t)j);
                c += (u >= t);
            }
        }
        c = block_sum128(c, s_ws);
        if (c >= k) lo = mid; else hi = mid - 1u;
    }
    return __uint_as_float(lo);
}

// ---------------------------------------------------------------------------
// Fused kernel: scan + default-fill; the 16th-arriving block of each row
// performs the row finalize inline (overlapped with other blocks' scans).
// grid = NROWS*SLICES = 3072 blocks, 128 threads.
// __launch_bounds__(128, 16): cap regs at 32 -> 16 blocks/SM (64 warps, full
// residency). Spills land in the cold finalize tail only.
// ---------------------------------------------------------------------------
__global__ __launch_bounds__(TPB, 16)
void fused_kernel(const float* __restrict__ g_ov,
                  const float* __restrict__ g_io,
                  const float* __restrict__ g_nm,
                  float* __restrict__ g_out,
                  Keys keys)
{
    __shared__ uint16_t s_q[NWARPS][WCHUNK];   // 8 KB
    __shared__ int   s_cp, s_cn;
    __shared__ float s_wmax[NWARPS];
    __shared__ float s_womax[NWARPS];
    __shared__ int   s_welig[NWARPS];
    __shared__ int   s_lastblk;
    // finalize scratch
    __shared__ int   s_ws[NWARPS];
    __shared__ float s_wf[NWARPS];
    __shared__ int   s_pc[SLICES], s_nc[SLICES], s_el[SLICES];
    __shared__ float s_m[SLICES], s_om[SLICES];

    const int tid   = threadIdx.x;
    const int wid   = tid >> 5;
    const int lane  = tid & 31;
    const int blk   = blockIdx.x;
    const int r     = blk >> 4;
    const int slice = blk & (SLICES - 1);
    const int h     = r % 3;
    const int b     = r / 3;

    const float POS_T = c_POS_T[h];
    const float NEG_T = c_NEG_T[h];
    const uint32_t k0 = keys.k0[h];
    const uint32_t k1 = keys.k1[h];
    const uint32_t rng_base = (uint32_t)b * (uint32_t)NROI;

    if (tid == 0) { s_cp = 0; s_cn = 0; }
    __syncthreads();

    const int chunk0 = slice * SLICE_ELEMS + wid * WCHUNK;
    const float4* ov4 = (const float4*)(g_ov + (size_t)r * NROI) + (chunk0 >> 2);
    const float4* io4 = (const float4*)(g_io + (size_t)r * NROI) + (chunk0 >> 2);
    float4* out4 = (float4*)(g_out + (size_t)r * NROI) + (chunk0 >> 2);
    const float4 NEG1 = make_float4(-1.0f, -1.0f, -1.0f, -1.0f);

    const unsigned lmask = (1u << lane) - 1u;
    float lmax = 0.0f;     // max iou
    float lomax = 0.0f;    // max overlap  (poscnt>0  <=>  lomax >= POS_T)
    int cnt = 0;

    // ---------- Phase A: scan + compact + default-fill ----------
#pragma unroll 4
    for (int it = 0; it < WCHUNK / 4 / 32; it++) {   // 8 iters
        int q = it * 32 + lane;
        float4 o4 = ov4[q];
        float4 v4 = io4[q];
        out4[q] = NEG1;                              // default label
        int local = q * 4;
#pragma unroll
        for (int l = 0; l < 4; l++) {
            float o = (&o4.x)[l];
            float v = (&v4.x)[l];
            lmax = fmaxf(lmax, v);
            lomax = fmaxf(lomax, o);
            if (v >= TPOSC && o >= POS_T) {          // ~0.4% of elements
                int p = atomicAdd(&s_cp, 1);
                if (p < PCAP) {
                    g_posv[r * NSLOT + slice * PCAP + p] = v;
                    g_posi[r * NSLOT + slice * PCAP + p] = chunk0 + local + l;
                }
            }
            bool el = (o <= NEG_T);
            unsigned m = __ballot_sync(0xFFFFFFFFu, el);
            if (el) s_q[wid][cnt + __popc(m & lmask)] = (uint16_t)(local + l);
            cnt += __popc(m);
        }
    }
    __syncwarp();

    // ---------- Phase B: dense hashing of compacted queue ----------
    const uint32_t jwbase = rng_base + (uint32_t)chunk0;
    for (int t = lane; t < cnt; t += 32) {
        uint32_t idx = (uint32_t)s_q[wid][t];
        float u = u01(k0, k1, jwbase + idx);
        if (u >= TNEGC) {                            // ~1% of eligible
            int p = atomicAdd(&s_cn, 1);
            if (p < NCAP) {
                g_negu[r * NSLOT + slice * NCAP + p] = u;
                g_negj[r * NSLOT + slice * NCAP + p] = (int)(chunk0 + idx);
            }
        }
    }

    // ---------- per-block reductions + metadata store ----------
    unsigned wmaxb  = __reduce_max_sync(0xFFFFFFFFu, __float_as_uint(lmax));
    unsigned womaxb = __reduce_max_sync(0xFFFFFFFFu, __float_as_uint(lomax));
    if (lane == 0) {
        s_wmax[wid]  = __uint_as_float(wmaxb);
        s_womax[wid] = __uint_as_float(womaxb);
        s_welig[wid] = cnt;
    }
    __syncthreads();
    if (tid == 0) {
        float mxv = 0.0f, omxv = 0.0f; int ec = 0;
#pragma unroll
        for (int w = 0; w < NWARPS; w++) {
            mxv = fmaxf(mxv, s_wmax[w]);
            omxv = fmaxf(omxv, s_womax[w]);
            ec += s_welig[w];
        }
        g_pmax[blk] = mxv;
        g_pomax[blk] = omxv;
        g_pelig[blk] = ec;
        g_pcnt[blk] = s_cp;
        g_ncnt[blk] = s_cn;
    }

    // ---------- last-block-arrives handoff ----------
    __threadfence();                 // publish this block's writes
    __syncthreads();                 // all threads fenced before the atomic
    if (tid == 0) {
        int old = atomicAdd(&g_arrive[r], 1);
        s_lastblk = (old == SLICES - 1);
    }
    __syncthreads();
    if (!s_lastblk) return;
    __threadfence();                 // acquire side

    // =================== FINALIZE row r (this block only) ===================
    const float IOU_T = c_IOU_T[h];
    const float* ov = g_ov + (size_t)r * NROI;
    const float* io = g_io + (size_t)r * NROI;
    const float* nm = g_nm + (size_t)r * NROI;
    float*       out = g_out + (size_t)r * NROI;

    if (tid < SLICES) {
        int bk = r * SLICES + tid;
        s_pc[tid] = __ldcg(&g_pcnt[bk]);
        s_nc[tid] = __ldcg(&g_ncnt[bk]);
        s_el[tid] = __ldcg(&g_pelig[bk]);
        s_m[tid]  = __ldcg(&g_pmax[bk]);
        s_om[tid] = __ldcg(&g_pomax[bk]);
    }
    __syncthreads();

    float mx = 0.0f, omx = 0.0f;
    int eligcnt = 0, cp = 0, cnn = 0, ovfP = 0, ovfN = 0;
#pragma unroll
    for (int s = 0; s < SLICES; s++) {
        mx = fmaxf(mx, s_m[s]); omx = fmaxf(omx, s_om[s]);
        eligcnt += s_el[s];
        cp += s_pc[s]; cnn += s_nc[s];
        ovfP |= (s_pc[s] > PCAP); ovfN |= (s_nc[s] > NCAP);
    }
    const int nopos = (omx < POS_T);     // poscnt == 0  <=>  max(ov) < POS_T
    const bool fast = (!nopos) && cp >= 16 && !ovfP &&
                      (eligcnt >= 48) && cnn >= 48 && !ovfN;

    if (fast) {
        // ---- positives: t16 (+top2) over candidates, scatter ----
        float v[VPT];
#pragma unroll
        for (int s = 0; s < VPT; s++) {
            int slot = s * TPB + tid;            // coalesced
            bool valid = (slot & (PCAP - 1)) < s_pc[slot >> 6];
            v[s] = valid ? __ldcg(&g_posv[r * NSLOT + slot]) : -1.0f;
        }
        float t16 = block_kth8(16, v, BITS_CAND, BITS_ONE, s_ws);
        float tk = (t16 >= IOU_T) ? t16 : IOU_T;
        float top2 = (h == 0) ? block_top2_8(v, s_ws, s_wf) : 0.0f;
#pragma unroll
        for (int s = 0; s < VPT; s++) {
            bool sel = (v[s] >= tk) || (h == 0 && v[s] > top2);
            if (sel) {                           // invalid (-1) never selects
                int pj = __ldcg(&g_posi[r * NSLOT + s * TPB + tid]);
                out[pj] = -1.0f + 2.0f * nm[pj];
            }
        }
        // ---- negatives: kth48 over candidates, scatter ----
        float uu[VPT];
#pragma unroll
        for (int s = 0; s < VPT; s++) {
            int slot = s * TPB + tid;
            bool valid = (slot & (NCAP - 1)) < s_nc[slot >> 6];
            uu[s] = valid ? __ldcg(&g_negu[r * NSLOT + slot]) : -1.0f;
        }
        float kth = block_kth8(48, uu, BITS_CAND, BITS_ONE, s_ws);
#pragma unroll
        for (int s = 0; s < VPT; s++) {
            if (uu[s] >= kth) {
                int nj = __ldcg(&g_negj[r * NSLOT + s * TPB + tid]);
                out[nj] = 0.0f;                  // -1 + 1; disjoint from pos
            }
        }
    } else {
        // ---------------- slow path: exact full-row rewrite ----------------
        float t16 = kth_bs_iomask(16, ov, io, POS_T, nopos, mx, s_ws);
        float top2 = 0.0f;
        if (h == 0) top2 = kth_bs_iomask(2, ov, io, POS_T, nopos, mx, s_ws);
        float tk = (t16 >= IOU_T) ? t16 : IOU_T;

        float kth = -1.0f;
        int allelig = (eligcnt < 48);
        if (!allelig)
            kth = kth_bs_score(48, ov, NEG_T, k0, k1, rng_base, s_ws);

        const float4* ovr4 = (const float4*)ov;
        const float4* ior4 = (const float4*)io;
        float4* outr4 = (float4*)out;
        for (int q = tid; q < NROI / 4; q += TPB) {
            float4 o4 = ovr4[q];
            float4 v4 = ior4[q];
            float4 res;
#pragma unroll
            for (int l = 0; l < 4; l++) {
                int j = q * 4 + l;
                float o = (&o4.x)[l];
                float v = (&v4.x)[l];
                float im = nopos ? ((v >= mx) ? v : 0.0f)
                                 : ((o >= POS_T) ? v : 0.0f);
                bool posb = (im >= tk);
                if (h == 0) posb = posb || (im > top2);
                float posf = 0.0f;
                if (posb) posf = nm[j];

                float negf = 0.0f;
                if (o <= NEG_T) {
                    if (allelig) negf = 1.0f;
                    else {
                        float u = u01(k0, k1, rng_base + (uint32_t)j);
                        if (u >= kth) negf = 1.0f;
                    }
                }
                (&res.x)[l] = (-1.0f + negf) + 2.0f * posf;
            }
            outr4[q] = res;
        }
    }

    __syncthreads();
    if (tid == 0) g_arrive[r] = 0;   // reset for next graph replay
}

// ---------------------------------------------------------------------------
// Launch — single fused kernel
// ---------------------------------------------------------------------------
extern "C" void kernel_launch(void* const* d_in, const int* in_sizes, int n_in,
                              void* d_out, int out_size)
{
    const float* ov = (const float*)d_in[0];
    const float* io = (const float*)d_in[1];
    const float* nm = (const float*)d_in[2];
    float* out = (float*)d_out;

    Keys keys;
    for (int h = 0; h < NCASC; h++) {
        uint32_t a, c;
        threefry2x32(0u, 42u, 0u, (uint32_t)h, a, c);
        keys.k0[h] = a;
        keys.k1[h] = c;
    }

    fused_kernel<<<NROWS * SLICES, TPB>>>(ov, io, nm, out, keys);
}

// round 14
// speedup vs baseline: 1.2730x; 1.2730x over previous
#include <cuda_runtime.h>
#include <stdint.h>

#define NROI    65536
#define NCASC   3
#define NBATCH  64
#define NROWS   (NBATCH * NCASC)
#define SLICES  32
#define SLICE_ELEMS (NROI / SLICES)        // 2048
#define SCAN_TPB 128
#define SCAN_WARPS (SCAN_TPB / 32)         // 4
#define WCHUNK  (SLICE_ELEMS / SCAN_WARPS) // 512 elements per warp
#define A2_TPB  1024
#define PCAP    32                         // pos candidates per (row,slice)
#define NCAP    32                         // neg candidates per (row,slice)
#define NSLOT   (SLICES * PCAP)            // 1024 candidate slots per row
#define TPOSC   0.99f
#define TNEGC   0.99f
#define BITS_CAND 0x3F7AE148u              // bits(0.98) — safe lower bound
#define BITS_ONE  0x3F800000u              // bits(1.0)  — values strictly below

struct Keys { uint32_t k0[3]; uint32_t k1[3]; };

// per-(row,slice) partials — written unconditionally every run (no init pass)
__device__ float  g_pmax [NROWS * SLICES];   // max iou per slice
__device__ float  g_pomax[NROWS * SLICES];   // max overlap per slice
__device__ int    g_pelig[NROWS * SLICES];
__device__ int    g_pcnt [NROWS * SLICES];
__device__ int    g_ncnt [NROWS * SLICES];
__device__ float  g_posv [NROWS * NSLOT];
__device__ int    g_posi [NROWS * NSLOT];
__device__ float  g_negu [NROWS * NSLOT];
__device__ int    g_negj [NROWS * NSLOT];

__device__ const float c_POS_T[3] = {0.6f, 0.7f, 0.8f};
__device__ const float c_IOU_T[3] = {0.2f, 0.3f, 0.4f};
__device__ const float c_NEG_T[3] = {0.3f, 0.3f, 0.3f};

// ---------------------------------------------------------------------------
// JAX threefry2x32 (exact; verified rel_err = 0.0)
// ---------------------------------------------------------------------------
__host__ __device__ __forceinline__ void threefry2x32(
    uint32_t k0, uint32_t k1, uint32_t x0, uint32_t x1,
    uint32_t& o0, uint32_t& o1)
{
    uint32_t ks2 = k0 ^ k1 ^ 0x1BD11BDAu;
    x0 += k0; x1 += k1;
#define TFR(r) { x0 += x1; x1 = (x1 << (r)) | (x1 >> (32 - (r))); x1 ^= x0; }
    TFR(13) TFR(15) TFR(26) TFR(6)  x0 += k1;  x1 += ks2 + 1u;
    TFR(17) TFR(29) TFR(16) TFR(24) x0 += ks2; x1 += k0  + 2u;
    TFR(13) TFR(15) TFR(26) TFR(6)  x0 += k0;  x1 += k1  + 3u;
    TFR(17) TFR(29) TFR(16) TFR(24) x0 += k1;  x1 += ks2 + 4u;
    TFR(13) TFR(15) TFR(26) TFR(6)  x0 += ks2; x1 += k0  + 5u;
#undef TFR
    o0 = x0; o1 = x1;
}

__device__ __forceinline__ float u01(uint32_t k0, uint32_t k1, uint32_t idx)
{
    uint32_t a, c;
    threefry2x32(k0, k1, 0u, idx, a, c);
    uint32_t bits = a ^ c;
    return __uint_as_float((bits >> 9) | 0x3F800000u) - 1.0f;
}

// ---------------------------------------------------------------------------
// kth-largest via binary search on float bit patterns, counting with
// __syncthreads_count (block-wide, no smem, no sort). Exact.
// Precondition: count(myval >= uint_as_float(lo)) >= k  (block-uniform args).
// ---------------------------------------------------------------------------
__device__ float block_kth(int k, float myval, unsigned lo, unsigned hi)
{
    while (hi > lo) {
        unsigned mid = lo + ((hi - lo + 1u) >> 1);
        int c = __syncthreads_count(myval >= __uint_as_float(mid));
        if (c >= k) lo = mid; else hi = mid - 1u;
    }
    return __uint_as_float(lo);
}

// ---------------------------------------------------------------------------
// Exact fallbacks over the full row (statistically never run)
// ---------------------------------------------------------------------------
__device__ __noinline__ float kth_bs_iomask(int k, const float* ov,
                                            const float* io, float POS_T,
                                            int nopos, float mx)
{
    __shared__ int s_ws[32];
    unsigned lo = 0u, hi = 0x7F800000u;
    while (hi > lo) {
        unsigned mid = lo + ((hi - lo + 1u) >> 1);
        float t = __uint_as_float(mid);
        int c = 0;
        for (int j = threadIdx.x; j < NROI; j += A2_TPB) {
            float o = ov[j], v = io[j];
            float im = nopos ? ((v >= mx) ? v : 0.0f)
                             : ((o >= POS_T) ? v : 0.0f);
            c += (im >= t);
        }
        c = (int)__reduce_add_sync(0xFFFFFFFFu, (unsigned)c);
        if ((threadIdx.x & 31) == 0) s_ws[threadIdx.x >> 5] = c;
        __syncthreads();
        if (threadIdx.x == 0) {
            int tot = 0;
            for (int w = 0; w < A2_TPB / 32; w++) tot += s_ws[w];
            s_ws[0] = tot;
        }
        __syncthreads();
        c = s_ws[0];
        __syncthreads();
        if (c >= k) lo = mid; else hi = mid - 1u;
    }
    return __uint_as_float(lo);
}

__device__ __noinline__ float kth_bs_score(int k, const float* ov, float NEG_T,
                                           uint32_t k0, uint32_t k1,
                                           uint32_t rng_base)
{
    __shared__ int s_ws[32];
    unsigned lo = 0u, hi = 0x7F800000u;
    while (hi > lo) {
        unsigned mid = lo + ((hi - lo + 1u) >> 1);
        float t = __uint_as_float(mid);
        int c = 0;
        for (int j = threadIdx.x; j < NROI; j += A2_TPB) {
            float o = ov[j];
            if (o <= NEG_T) {
                float u = u01(k0, k1, rng_base + (uint32_t)j);
                c += (u >= t);
            }
        }
        c = (int)__reduce_add_sync(0xFFFFFFFFu, (unsigned)c);
        if ((threadIdx.x & 31) == 0) s_ws[threadIdx.x >> 5] = c;
        __syncthreads();
        if (threadIdx.x == 0) {
            int tot = 0;
            for (int w = 0; w < A2_TPB / 32; w++) tot += s_ws[w];
            s_ws[0] = tot;
        }
        __syncthreads();
        c = s_ws[0];
        __syncthreads();
        if (c >= k) lo = mid; else hi = mid - 1u;
    }
    return __uint_as_float(lo);
}

// ---------------------------------------------------------------------------
// Kernel A: scan + default-fill. grid = NROWS*SLICES = 6144 blocks, 128 thr.
// Smaller slices halve per-block latency -> smaller last-wave tail.
// Streaming cache hints: inputs read-once (__ldcs), output write-once (__stcs).
// ---------------------------------------------------------------------------
__global__ __launch_bounds__(SCAN_TPB)
void scan_kernel(const float* __restrict__ g_ov,
                 const float* __restrict__ g_io,
                 float* __restrict__ g_out,
                 Keys keys)
{
    __shared__ uint16_t s_q[SCAN_WARPS][WCHUNK];   // 4 KB
    __shared__ int   s_cp, s_cn;
    __shared__ float s_wmax[SCAN_WARPS];
    __shared__ float s_womax[SCAN_WARPS];
    __shared__ int   s_welig[SCAN_WARPS];

    const int tid   = threadIdx.x;
    const int wid   = tid >> 5;
    const int lane  = tid & 31;
    const int blk   = blockIdx.x;
    const int r     = blk >> 5;
    const int slice = blk & (SLICES - 1);
    const int h     = r % 3;
    const int b     = r / 3;

    const float POS_T = c_POS_T[h];
    const float NEG_T = c_NEG_T[h];
    const uint32_t k0 = keys.k0[h];
    const uint32_t k1 = keys.k1[h];
    const uint32_t rng_base = (uint32_t)b * (uint32_t)NROI;

    if (tid == 0) { s_cp = 0; s_cn = 0; }
    __syncthreads();

    const int chunk0 = slice * SLICE_ELEMS + wid * WCHUNK;
    const float4* ov4 = (const float4*)(g_ov + (size_t)r * NROI) + (chunk0 >> 2);
    const float4* io4 = (const float4*)(g_io + (size_t)r * NROI) + (chunk0 >> 2);
    float4* out4 = (float4*)(g_out + (size_t)r * NROI) + (chunk0 >> 2);
    const float4 NEG1 = make_float4(-1.0f, -1.0f, -1.0f, -1.0f);

    const unsigned lmask = (1u << lane) - 1u;
    float lmax = 0.0f;     // max iou
    float lomax = 0.0f;    // max overlap  (poscnt>0  <=>  lomax >= POS_T)
    int cnt = 0;

    // ---------- Phase A: scan + compact + default-fill ----------
#pragma unroll
    for (int it = 0; it < WCHUNK / 4 / 32; it++) {   // 4 iters (fully unrolled)
        int q = it * 32 + lane;
        float4 o4 = __ldcs(&ov4[q]);
        float4 v4 = __ldcs(&io4[q]);
        __stcs(&out4[q], NEG1);                      // default label
        int local = q * 4;
#pragma unroll
        for (int l = 0; l < 4; l++) {
            float o = (&o4.x)[l];
            float v = (&v4.x)[l];
            lmax = fmaxf(lmax, v);
            lomax = fmaxf(lomax, o);
            if (v >= TPOSC && o >= POS_T) {          // ~0.4% of elements
                int p = atomicAdd(&s_cp, 1);
                if (p < PCAP) {
                    g_posv[r * NSLOT + slice * PCAP + p] = v;
                    g_posi[r * NSLOT + slice * PCAP + p] = chunk0 + local + l;
                }
            }
            bool el = (o <= NEG_T);
            unsigned m = __ballot_sync(0xFFFFFFFFu, el);
            if (el) s_q[wid][cnt + __popc(m & lmask)] = (uint16_t)(local + l);
            cnt += __popc(m);
        }
    }
    __syncwarp();

    // ---------- Phase B: dense hashing of compacted queue ----------
    const uint32_t jwbase = rng_base + (uint32_t)chunk0;
    for (int t = lane; t < cnt; t += 32) {
        uint32_t idx = (uint32_t)s_q[wid][t];
        float u = u01(k0, k1, jwbase + idx);
        if (u >= TNEGC) {                            // ~1% of eligible
            int p = atomicAdd(&s_cn, 1);
            if (p < NCAP) {
                g_negu[r * NSLOT + slice * NCAP + p] = u;
                g_negj[r * NSLOT + slice * NCAP + p] = (int)(chunk0 + idx);
            }
        }
    }

    // ---------- reductions ----------
    unsigned wmaxb  = __reduce_max_sync(0xFFFFFFFFu, __float_as_uint(lmax));
    unsigned womaxb = __reduce_max_sync(0xFFFFFFFFu, __float_as_uint(lomax));
    if (lane == 0) {
        s_wmax[wid]  = __uint_as_float(wmaxb);
        s_womax[wid] = __uint_as_float(womaxb);
        s_welig[wid] = cnt;
    }
    __syncthreads();
    if (tid == 0) {
        float mx = 0.0f, omx = 0.0f; int ec = 0;
#pragma unroll
        for (int w = 0; w < SCAN_WARPS; w++) {
            mx = fmaxf(mx, s_wmax[w]);
            omx = fmaxf(omx, s_womax[w]);
            ec += s_welig[w];
        }
        g_pmax[blk] = mx;
        g_pomax[blk] = omx;
        g_pelig[blk] = ec;
        g_pcnt[blk] = s_cp;
        g_ncnt[blk] = s_cn;
    }
}

// ---------------------------------------------------------------------------
// Kernel B: per-row finalize + scatter. grid = NROWS, 1024 threads.
// Order statistics via __syncthreads_count binary search (R10-proven).
// Fast path scatters ~65 stores over the -1 default; slow path rewrites row.
// ---------------------------------------------------------------------------
__global__ __launch_bounds__(A2_TPB)
void finalize_kernel(const float* __restrict__ g_ov,
                     const float* __restrict__ g_io,
                     const float* __restrict__ g_nm,
                     float* __restrict__ g_out,
                     Keys keys)
{
    __shared__ int   s_pcnt[SLICES], s_ncnt[SLICES];
    __shared__ float s_mxs[SLICES], s_omxs[SLICES];
    __shared__ int   s_eligs[SLICES];
    __shared__ float s_mx, s_omx;
    __shared__ int   s_eligcnt, s_cp, s_cn, s_ovfP, s_ovfN;

    const int tid = threadIdx.x;
    const int r = blockIdx.x;
    const int h = r % 3;
    const int b = r / 3;

    const float POS_T = c_POS_T[h];
    const float NEG_T = c_NEG_T[h];
    const float IOU_T = c_IOU_T[h];
    const uint32_t k0 = keys.k0[h];
    const uint32_t k1 = keys.k1[h];
    const uint32_t rng_base = (uint32_t)b * (uint32_t)NROI;

    const float* ov = g_ov + (size_t)r * NROI;
    const float* io = g_io + (size_t)r * NROI;
    const float* nm = g_nm + (size_t)r * NROI;
    float*       out = g_out + (size_t)r * NROI;

    if (tid < SLICES) {
        int blk = r * SLICES + tid;
        s_pcnt[tid] = g_pcnt[blk];
        s_ncnt[tid] = g_ncnt[blk];
        s_mxs[tid]  = g_pmax[blk];
        s_omxs[tid] = g_pomax[blk];
        s_eligs[tid]= g_pelig[blk];
    }
    __syncthreads();
    if (tid == 0) {
        float mx = 0.0f, omx = 0.0f; int ec = 0, cp = 0, cn = 0, op = 0, on = 0;
#pragma unroll
        for (int s = 0; s < SLICES; s++) {
            mx = fmaxf(mx, s_mxs[s]); omx = fmaxf(omx, s_omxs[s]);
            ec += s_eligs[s];
            cp += s_pcnt[s]; cn += s_ncnt[s];
            op |= (s_pcnt[s] > PCAP); on |= (s_ncnt[s] > NCAP);
        }
        s_mx = mx; s_omx = omx; s_eligcnt = ec;
        s_cp = cp; s_cn = cn; s_ovfP = op; s_ovfN = on;
    }
    __syncthreads();

    const float mx = s_mx;
    const int eligcnt = s_eligcnt;
    const int cp = s_cp, cn = s_cn, ovfP = s_ovfP, ovfN = s_ovfN;
    const int nopos = (s_omx < POS_T);   // poscnt == 0  <=>  max(ov) < POS_T

    // candidate regs (slot layout: SLICES*PCAP = 1024 = A2_TPB, 1 slot/thread)
    const int psl = tid >> 5, pi = tid & (PCAP - 1);
    const bool pvalid = (pi < s_pcnt[psl]);
    float pv_reg = pvalid ? g_posv[r * NSLOT + tid] : -1.0f;
    int   pj_reg = pvalid ? g_posi[r * NSLOT + tid] : 0;

    const int nsl = tid >> 5, ni = tid & (NCAP - 1);
    const bool nvalid = (ni < s_ncnt[nsl]);
    float nu_reg = nvalid ? g_negu[r * NSLOT + tid] : -1.0f;
    int   nj_reg = nvalid ? g_negj[r * NSLOT + tid] : 0;

    // -------- positive threshold: 16th (+2nd) largest of iou_masked --------
    int posfast = 0;
    float t16, top2 = 0.0f;
    if (!nopos && cp >= 16 && !ovfP) {
        posfast = 1;
        t16 = block_kth(16, pv_reg, BITS_CAND, BITS_ONE);
        if (h == 0) top2 = block_kth(2, pv_reg, BITS_CAND, BITS_ONE);
    } else {
        t16 = kth_bs_iomask(16, ov, io, POS_T, nopos, mx);
        if (h == 0) top2 = kth_bs_iomask(2, ov, io, POS_T, nopos, mx);
    }
    float tk = (t16 >= IOU_T) ? t16 : IOU_T;

    // -------- negative threshold: 48th largest random score among eligible --
    float kth = -1.0f;
    int negmode;  // 0 = list, 1 = all-eligible, 2 = slow
    if (eligcnt < 48) {
        negmode = 1;
    } else if (cn >= 48 && !ovfN) {
        negmode = 0;
        kth = block_kth(48, nu_reg, BITS_CAND, BITS_ONE);
    } else {
        negmode = 2;
        kth = kth_bs_score(48, ov, NEG_T, k0, k1, rng_base);
    }

    // ---------------- fast path: scatter over -1 default ----------------
    if (posfast && negmode == 0) {
        if (nvalid && nu_reg >= kth)
            out[nj_reg] = 0.0f;                      // -1 + 1; disjoint from pos
        bool posb = pvalid && ((pv_reg >= tk) || (h == 0 && pv_reg > top2));
        if (posb)
            out[pj_reg] = -1.0f + 2.0f * nm[pj_reg];
        return;
    }

    // ---------------- slow path: rewrite whole row exactly ----------------
    const float4* ov4 = (const float4*)ov;
    const float4* io4 = (const float4*)io;
    float4* out4 = (float4*)out;
    for (int q = tid; q < NROI / 4; q += A2_TPB) {
        float4 o4 = ov4[q];
        float4 v4 = io4[q];
        float4 res;
#pragma unroll
        for (int l = 0; l < 4; l++) {
            int j = q * 4 + l;
            float o = (&o4.x)[l];
            float v = (&v4.x)[l];
            float im = nopos ? ((v >= mx) ? v : 0.0f)
                             : ((o >= POS_T) ? v : 0.0f);
            bool posb = (im >= tk);
            if (h == 0) posb = posb || (im > top2);
            float posf = 0.0f;
            if (posb) posf = nm[j];

            float negf = 0.0f;
            if (o <= NEG_T) {
                if (negmode == 1) {
                    negf = 1.0f;
                } else {
                    float u = u01(k0, k1, rng_base + (uint32_t)j);
                    if (u >= kth) negf = 1.0f;
                }
            }
            (&res.x)[l] = (-1.0f + negf) + 2.0f * posf;
        }
        out4[q] = res;
    }
}

// ---------------------------------------------------------------------------
// Launch
// ---------------------------------------------------------------------------
extern "C" void kernel_launch(void* const* d_in, const int* in_sizes, int n_in,
                              void* d_out, int out_size)
{
    const float* ov = (const float*)d_in[0];
    const float* io = (const float*)d_in[1];
    const float* nm = (const float*)d_in[2];
    float* out = (float*)d_out;

    Keys keys;
    for (int h = 0; h < NCASC; h++) {
        uint32_t a, c;
        threefry2x32(0u, 42u, 0u, (uint32_t)h, a, c);
        keys.k0[h] = a;
        keys.k1[h] = c;
    }

    scan_kernel<<<NROWS * SLICES, SCAN_TPB>>>(ov, io, out, keys);
    finalize_kernel<<<NROWS, A2_TPB>>>(ov, io, nm, out, keys);
}

// round 15
// speedup vs baseline: 1.4156x; 1.1121x over previous
#include <cuda_runtime.h>
#include <stdint.h>

#define NROI    65536
#define NCASC   3
#define NBATCH  64
#define NROWS   (NBATCH * NCASC)
#define SLICES  32
#define SLICE_ELEMS (NROI / SLICES)        // 2048
#define SCAN_TPB 128
#define SCAN_WARPS (SCAN_TPB / 32)         // 4
#define WCHUNK  (SLICE_ELEMS / SCAN_WARPS) // 512 elements per warp
#define FIN_TPB 256
#define PCAP    32                         // pos candidates per (row,slice)
#define NCAP    32                         // neg candidates per (row,slice)
#define NSLOT   (SLICES * PCAP)            // 1024 candidate slots per row
#define TPOSC   0.99f
#define TNEGC   0.99f
#define BITS_CAND 0x3F7AE148u              // bits(0.98) — safe lower bound
#define BITS_ONE  0x3F800000u              // bits(1.0)  — values strictly below

struct Keys { uint32_t k0[3]; uint32_t k1[3]; };

// per-(row,slice) partials — written unconditionally every run (no init pass)
__device__ float  g_pmax [NROWS * SLICES];   // max iou per slice
__device__ float  g_pomax[NROWS * SLICES];   // max overlap per slice
__device__ int    g_pelig[NROWS * SLICES];
__device__ int    g_pcnt [NROWS * SLICES];
__device__ int    g_ncnt [NROWS * SLICES];
__device__ float  g_posv [NROWS * NSLOT];
__device__ int    g_posi [NROWS * NSLOT];
__device__ float  g_negu [NROWS * NSLOT];
__device__ int    g_negj [NROWS * NSLOT];

__device__ const float c_POS_T[3] = {0.6f, 0.7f, 0.8f};
__device__ const float c_IOU_T[3] = {0.2f, 0.3f, 0.4f};
__device__ const float c_NEG_T[3] = {0.3f, 0.3f, 0.3f};

// ---------------------------------------------------------------------------
// JAX threefry2x32 (exact; verified rel_err = 0.0)
// ---------------------------------------------------------------------------
__host__ __device__ __forceinline__ void threefry2x32(
    uint32_t k0, uint32_t k1, uint32_t x0, uint32_t x1,
    uint32_t& o0, uint32_t& o1)
{
    uint32_t ks2 = k0 ^ k1 ^ 0x1BD11BDAu;
    x0 += k0; x1 += k1;
#define TFR(r) { x0 += x1; x1 = (x1 << (r)) | (x1 >> (32 - (r))); x1 ^= x0; }
    TFR(13) TFR(15) TFR(26) TFR(6)  x0 += k1;  x1 += ks2 + 1u;
    TFR(17) TFR(29) TFR(16) TFR(24) x0 += ks2; x1 += k0  + 2u;
    TFR(13) TFR(15) TFR(26) TFR(6)  x0 += k0;  x1 += k1  + 3u;
    TFR(17) TFR(29) TFR(16) TFR(24) x0 += k1;  x1 += ks2 + 4u;
    TFR(13) TFR(15) TFR(26) TFR(6)  x0 += ks2; x1 += k0  + 5u;
#undef TFR
    o0 = x0; o1 = x1;
}

__device__ __forceinline__ float u01(uint32_t k0, uint32_t k1, uint32_t idx)
{
    uint32_t a, c;
    threefry2x32(k0, k1, 0u, idx, a, c);
    uint32_t bits = a ^ c;
    return __uint_as_float((bits >> 9) | 0x3F800000u) - 1.0f;
}

// ---------------------------------------------------------------------------
// Warp-local kth-largest over 32 register slots/lane (invalid slots = -1).
// Binary search on float bits; counting via __reduce_add_sync. No barriers.
// Exact. Precondition: count(v >= uint_as_float(lo)) >= k.
// ---------------------------------------------------------------------------
__device__ float warp_kth(int k, const float (&v)[32], unsigned lo, unsigned hi)
{
    while (hi > lo) {
        unsigned mid = lo + ((hi - lo + 1u) >> 1);
        float t = __uint_as_float(mid);
        int c = 0;
#pragma unroll
        for (int s = 0; s < 32; s++) c += (v[s] >= t);
        c = (int)__reduce_add_sync(0xFFFFFFFFu, (unsigned)c);
        if (c >= k) lo = mid; else hi = mid - 1u;
    }
    return __uint_as_float(lo);
}

// top_k[1] semantics: max if multiplicity >= 2, else largest strictly below.
__device__ float warp_top2(const float (&v)[32])
{
    float m1l = 0.0f;
#pragma unroll
    for (int s = 0; s < 32; s++) m1l = fmaxf(m1l, v[s]);
    float m1 = __uint_as_float(
        __reduce_max_sync(0xFFFFFFFFu, __float_as_uint(m1l)));
    int c1 = 0;
#pragma unroll
    for (int s = 0; s < 32; s++) c1 += (v[s] >= m1);
    c1 = (int)__reduce_add_sync(0xFFFFFFFFu, (unsigned)c1);
    if (c1 >= 2) return m1;
    float m2l = 0.0f;
#pragma unroll
    for (int s = 0; s < 32; s++) m2l = fmaxf(m2l, (v[s] < m1) ? v[s] : 0.0f);
    return __uint_as_float(
        __reduce_max_sync(0xFFFFFFFFu, __float_as_uint(m2l)));
}

// ---------------------------------------------------------------------------
// Exact full-row fallbacks (statistically never run). 256-thread block.
// ---------------------------------------------------------------------------
__device__ __forceinline__ int block_sum256(int c, int* s_ws)
{
    c = (int)__reduce_add_sync(0xFFFFFFFFu, (unsigned)c);
    if ((threadIdx.x & 31) == 0) s_ws[threadIdx.x >> 5] = c;
    __syncthreads();
    int tot = 0;
#pragma unroll
    for (int w = 0; w < FIN_TPB / 32; w++) tot += s_ws[w];
    __syncthreads();
    return tot;
}

__device__ __noinline__ float kth_bs_iomask(int k, const float* ov,
                                            const float* io, float POS_T,
                                            int nopos, float mx, int* s_ws)
{
    unsigned lo = 0u, hi = 0x7F800000u;
    while (hi > lo) {
        unsigned mid = lo + ((hi - lo + 1u) >> 1);
        float t = __uint_as_float(mid);
        int c = 0;
        for (int j = threadIdx.x; j < NROI; j += FIN_TPB) {
            float o = ov[j], v = io[j];
            float im = nopos ? ((v >= mx) ? v : 0.0f)
                             : ((o >= POS_T) ? v : 0.0f);
            c += (im >= t);
        }
        c = block_sum256(c, s_ws);
        if (c >= k) lo = mid; else hi = mid - 1u;
    }
    return __uint_as_float(lo);
}

__device__ __noinline__ float kth_bs_score(int k, const float* ov, float NEG_T,
                                           uint32_t k0, uint32_t k1,
                                           uint32_t rng_base, int* s_ws)
{
    unsigned lo = 0u, hi = 0x7F800000u;
    while (hi > lo) {
        unsigned mid = lo + ((hi - lo + 1u) >> 1);
        float t = __uint_as_float(mid);
        int c = 0;
        for (int j = threadIdx.x; j < NROI; j += FIN_TPB) {
            float o = ov[j];
            if (o <= NEG_T) {
                float u = u01(k0, k1, rng_base + (uint32_t)j);
                c += (u >= t);
            }
        }
        c = block_sum256(c, s_ws);
        if (c >= k) lo = mid; else hi = mid - 1u;
    }
    return __uint_as_float(lo);
}

// ---------------------------------------------------------------------------
// Kernel A: scan + default-fill. grid = NROWS*SLICES = 6144 blocks, 128 thr.
// (unchanged from R14 — matched the model)
// ---------------------------------------------------------------------------
__global__ __launch_bounds__(SCAN_TPB)
void scan_kernel(const float* __restrict__ g_ov,
                 const float* __restrict__ g_io,
                 float* __restrict__ g_out,
                 Keys keys)
{
    __shared__ uint16_t s_q[SCAN_WARPS][WCHUNK];   // 4 KB
    __shared__ int   s_cp, s_cn;
    __shared__ float s_wmax[SCAN_WARPS];
    __shared__ float s_womax[SCAN_WARPS];
    __shared__ int   s_welig[SCAN_WARPS];

    const int tid   = threadIdx.x;
    const int wid   = tid >> 5;
    const int lane  = tid & 31;
    const int blk   = blockIdx.x;
    const int r     = blk >> 5;
    const int slice = blk & (SLICES - 1);
    const int h     = r % 3;
    const int b     = r / 3;

    const float POS_T = c_POS_T[h];
    const float NEG_T = c_NEG_T[h];
    const uint32_t k0 = keys.k0[h];
    const uint32_t k1 = keys.k1[h];
    const uint32_t rng_base = (uint32_t)b * (uint32_t)NROI;

    if (tid == 0) { s_cp = 0; s_cn = 0; }
    __syncthreads();

    const int chunk0 = slice * SLICE_ELEMS + wid * WCHUNK;
    const float4* ov4 = (const float4*)(g_ov + (size_t)r * NROI) + (chunk0 >> 2);
    const float4* io4 = (const float4*)(g_io + (size_t)r * NROI) + (chunk0 >> 2);
    float4* out4 = (float4*)(g_out + (size_t)r * NROI) + (chunk0 >> 2);
    const float4 NEG1 = make_float4(-1.0f, -1.0f, -1.0f, -1.0f);

    const unsigned lmask = (1u << lane) - 1u;
    float lmax = 0.0f;     // max iou
    float lomax = 0.0f;    // max overlap  (poscnt>0  <=>  lomax >= POS_T)
    int cnt = 0;

    // ---------- Phase A: scan + compact + default-fill ----------
#pragma unroll
    for (int it = 0; it < WCHUNK / 4 / 32; it++) {   // 4 iters
        int q = it * 32 + lane;
        float4 o4 = __ldcs(&ov4[q]);
        float4 v4 = __ldcs(&io4[q]);
        __stcs(&out4[q], NEG1);                      // default label
        int local = q * 4;
#pragma unroll
        for (int l = 0; l < 4; l++) {
            float o = (&o4.x)[l];
            float v = (&v4.x)[l];
            lmax = fmaxf(lmax, v);
            lomax = fmaxf(lomax, o);
            if (v >= TPOSC && o >= POS_T) {          // ~0.4% of elements
                int p = atomicAdd(&s_cp, 1);
                if (p < PCAP) {
                    g_posv[r * NSLOT + slice * PCAP + p] = v;
                    g_posi[r * NSLOT + slice * PCAP + p] = chunk0 + local + l;
                }
            }
            bool el = (o <= NEG_T);
            unsigned m = __ballot_sync(0xFFFFFFFFu, el);
            if (el) s_q[wid][cnt + __popc(m & lmask)] = (uint16_t)(local + l);
            cnt += __popc(m);
        }
    }
    __syncwarp();

    // ---------- Phase B: dense hashing of compacted queue ----------
    const uint32_t jwbase = rng_base + (uint32_t)chunk0;
    for (int t = lane; t < cnt; t += 32) {
        uint32_t idx = (uint32_t)s_q[wid][t];
        float u = u01(k0, k1, jwbase + idx);
        if (u >= TNEGC) {                            // ~1% of eligible
            int p = atomicAdd(&s_cn, 1);
            if (p < NCAP) {
                g_negu[r * NSLOT + slice * NCAP + p] = u;
                g_negj[r * NSLOT + slice * NCAP + p] = (int)(chunk0 + idx);
            }
        }
    }

    // ---------- reductions ----------
    unsigned wmaxb  = __reduce_max_sync(0xFFFFFFFFu, __float_as_uint(lmax));
    unsigned womaxb = __reduce_max_sync(0xFFFFFFFFu, __float_as_uint(lomax));
    if (lane == 0) {
        s_wmax[wid]  = __uint_as_float(wmaxb);
        s_womax[wid] = __uint_as_float(womaxb);
        s_welig[wid] = cnt;
    }
    __syncthreads();
    if (tid == 0) {
        float mx = 0.0f, omx = 0.0f; int ec = 0;
#pragma unroll
        for (int w = 0; w < SCAN_WARPS; w++) {
            mx = fmaxf(mx, s_wmax[w]);
            omx = fmaxf(omx, s_womax[w]);
            ec += s_welig[w];
        }
        g_pmax[blk] = mx;
        g_pomax[blk] = omx;
        g_pelig[blk] = ec;
        g_pcnt[blk] = s_cp;
        g_ncnt[blk] = s_cn;
    }
}

// ---------------------------------------------------------------------------
// Kernel B: per-row finalize + scatter. grid = NROWS, 256 threads.
// Fast path: 3 barriers total. Candidates vector-loaded to smem; the three
// order statistics run concurrently on warps 0/1/2 (warp-local, barrier-free);
// all 256 threads scatter.
// ---------------------------------------------------------------------------
__global__ __launch_bounds__(FIN_TPB)
void finalize_kernel(const float* __restrict__ g_ov,
                     const float* __restrict__ g_io,
                     const float* __restrict__ g_nm,
                     float* __restrict__ g_out,
                     Keys keys)
{
    __shared__ float s_pv[NSLOT];
    __shared__ float s_nu[NSLOT];
    __shared__ int   s_pj[NSLOT];
    __shared__ int   s_nj[NSLOT];
    __shared__ int   s_pcnt[SLICES], s_ncnt[SLICES], s_eligs[SLICES];
    __shared__ float s_mxs[SLICES], s_omxs[SLICES];
    __shared__ float s_tk, s_top2, s_kth;
    __shared__ int   s_ws[FIN_TPB / 32];     // slow-path reduce scratch

    const int tid = threadIdx.x;
    const int wid = tid >> 5;
    const int lane = tid & 31;
    const int r = blockIdx.x;
    const int h = r % 3;
    const int b = r / 3;

    const float POS_T = c_POS_T[h];
    const float NEG_T = c_NEG_T[h];
    const float IOU_T = c_IOU_T[h];
    const uint32_t k0 = keys.k0[h];
    const uint32_t k1 = keys.k1[h];
    const uint32_t rng_base = (uint32_t)b * (uint32_t)NROI;

    const float* ov = g_ov + (size_t)r * NROI;
    const float* io = g_io + (size_t)r * NROI;
    const float* nm = g_nm + (size_t)r * NROI;
    float*       out = g_out + (size_t)r * NROI;

    // ---- metadata + candidate vector loads issued together (one round) ----
    if (tid < SLICES) {
        int blk = r * SLICES + tid;
        s_pcnt[tid] = g_pcnt[blk];
        s_ncnt[tid] = g_ncnt[blk];
        s_eligs[tid]= g_pelig[blk];
        s_mxs[tid]  = g_pmax[blk];
        s_omxs[tid] = g_pomax[blk];
    }
    float4 pv4 = ((const float4*)(g_posv + (size_t)r * NSLOT))[tid];
    int4   pj4 = ((const int4*)  (g_posi + (size_t)r * NSLOT))[tid];
    float4 nu4 = ((const float4*)(g_negu + (size_t)r * NSLOT))[tid];
    int4   nj4 = ((const int4*)  (g_negj + (size_t)r * NSLOT))[tid];
    __syncthreads();                                   // barrier 1

    // aggregates (each thread redundantly; registers, cheap)
    float mx = 0.0f, omx = 0.0f;
    int eligcnt = 0, cp = 0, cn = 0, ovfP = 0, ovfN = 0;
#pragma unroll
    for (int s = 0; s < SLICES; s++) {
        mx = fmaxf(mx, s_mxs[s]); omx = fmaxf(omx, s_omxs[s]);
        eligcnt += s_eligs[s];
        cp += s_pcnt[s]; cn += s_ncnt[s];
        ovfP |= (s_pcnt[s] > PCAP); ovfN |= (s_ncnt[s] > NCAP);
    }
    const int nopos = (omx < POS_T);     // poscnt == 0  <=>  max(ov) < POS_T
    const bool fast = (!nopos) && cp >= 16 && !ovfP &&
                      (eligcnt >= 48) && cn >= 48 && !ovfN;

    if (fast) {
        // stage masked candidates in smem (counts <= caps since !ovf)
#pragma unroll
        for (int l = 0; l < 4; l++) {
            int slot = tid * 4 + l;
            bool pval = (slot & (PCAP - 1)) < s_pcnt[slot >> 5];
            bool nval = (slot & (NCAP - 1)) < s_ncnt[slot >> 5];
            s_pv[slot] = pval ? (&pv4.x)[l] : -1.0f;
            s_pj[slot] = (&pj4.x)[l];
            s_nu[slot] = nval ? (&nu4.x)[l] : -1.0f;
            s_nj[slot] = (&nj4.x)[l];
        }
        __syncthreads();                               // barrier 2

        // three order statistics on three warps, concurrently, barrier-free
        if (wid < 3) {
            float v[32];
#pragma unroll
            for (int s = 0; s < 32; s++)
                v[s] = (wid == 2) ? s_nu[s * 32 + lane] : s_pv[s * 32 + lane];
            if (wid == 0) {
                float t16 = warp_kth(16, v, BITS_CAND, BITS_ONE);
                if (lane == 0) s_tk = (t16 >= IOU_T) ? t16 : IOU_T;
            } else if (wid == 1) {
                float t2 = (h == 0) ? warp_top2(v) : 0.0f;
                if (lane == 0) s_top2 = t2;
            } else {
                float kth = warp_kth(48, v, BITS_CAND, BITS_ONE);
                if (lane == 0) s_kth = kth;
            }
        }
        __syncthreads();                               // barrier 3

        const float tk = s_tk, top2 = s_top2, kth = s_kth;
        // scatter the ~65 differing labels over the -1 default
#pragma unroll
        for (int l = 0; l < 4; l++) {
            int slot = tid * 4 + l;
            if (s_nu[slot] >= kth)
                out[s_nj[slot]] = 0.0f;          // -1 + 1; disjoint from pos
            float v = s_pv[slot];
            bool posb = (v >= tk) || (h == 0 && v > top2);
            if (posb) {                          // invalid (-1) never selects
                int pj = s_pj[slot];
                out[pj] = -1.0f + 2.0f * nm[pj];
            }
        }
        return;
    }

    // ---------------- slow path: rewrite whole row exactly ----------------
    float t16 = kth_bs_iomask(16, ov, io, POS_T, nopos, mx, s_ws);
    float top2 = 0.0f;
    if (h == 0) top2 = kth_bs_iomask(2, ov, io, POS_T, nopos, mx, s_ws);
    float tk = (t16 >= IOU_T) ? t16 : IOU_T;

    float kth = -1.0f;
    int allelig = (eligcnt < 48);
    if (!allelig)
        kth = kth_bs_score(48, ov, NEG_T, k0, k1, rng_base, s_ws);

    const float4* ov4 = (const float4*)ov;
    const float4* io4 = (const float4*)io;
    float4* out4 = (float4*)out;
    for (int q = tid; q < NROI / 4; q += FIN_TPB) {
        float4 o4 = ov4[q];
        float4 v4 = io4[q];
        float4 res;
#pragma unroll
        for (int l = 0; l < 4; l++) {
            int j = q * 4 + l;
            float o = (&o4.x)[l];
            float v = (&v4.x)[l];
            float im = nopos ? ((v >= mx) ? v : 0.0f)
                             : ((o >= POS_T) ? v : 0.0f);
            bool posb = (im >= tk);
            if (h == 0) posb = posb || (im > top2);
            float posf = 0.0f;
            if (posb) posf = nm[j];

            float negf = 0.0f;
            if (o <= NEG_T) {
                if (allelig) negf = 1.0f;
                else {
                    float u = u01(k0, k1, rng_base + (uint32_t)j);
                    if (u >= kth) negf = 1.0f;
                }
            }
            (&res.x)[l] = (-1.0f + negf) + 2.0f * posf;
        }
        out4[q] = res;
    }
}

// ---------------------------------------------------------------------------
// Launch
// ---------------------------------------------------------------------------
extern "C" void kernel_launch(void* const* d_in, const int* in_sizes, int n_in,
                              void* d_out, int out_size)
{
    const float* ov = (const float*)d_in[0];
    const float* io = (const float*)d_in[1];
    const float* nm = (const float*)d_in[2];
    float* out = (float*)d_out;

    Keys keys;
    for (int h = 0; h < NCASC; h++) {
        uint32_t a, c;
        threefry2x32(0u, 42u, 0u, (uint32_t)h, a, c);
        keys.k0[h] = a;
        keys.k1[h] = c;
    }

    scan_kernel<<<NROWS * SLICES, SCAN_TPB>>>(ov, io, out, keys);
    finalize_kernel<<<NROWS, FIN_TPB>>>(ov, io, nm, out, keys);
}